// round 2
// baseline (speedup 1.0000x reference)
#include <cuda_runtime.h>
#include <cuda_bf16.h>
#include <cstdint>

#define DI __device__ __forceinline__

// Problem sizes (fixed by the dataset)
constexpr int D  = 2048;   // model dim
constexpr int Hh = 8192;   // hidden dim
constexpr int R  = 16;     // lora rank
constexpr int M  = 8192;   // B*S rows

// ---------------- scratch (device globals; no allocation allowed) ----------
__device__ __nv_bfloat16 g_Kx[M * D];                 // quantized x (ints in bf16)
__device__ __nv_bfloat16 g_Kwfc[Hh * D];              // quantized w_fc
__device__ __nv_bfloat16 g_Kwpr[D * Hh];              // quantized w_proj
__device__ float         g_h[(size_t)M * Hh];         // gelu output, fp32
__device__ __nv_bfloat16 g_Kh[(size_t)M * Hh];        // quantized h
__device__ float         g_t1[M * R];                 // x @ A_fc^T
__device__ float         g_t2[M * R];                 // h @ A_proj^T
__device__ float         g_tpart[32 * M * R];         // k-split partials
__device__ unsigned      g_amax[4];                   // |x|max, |w_fc|max, |w_proj|max, |h|max

// ---------------- small helpers -------------------------------------------
DI void cp16(void* s, const void* g) {
    uint32_t sa = (uint32_t)__cvta_generic_to_shared(s);
    asm volatile("cp.async.cg.shared.global [%0], [%1], 16;\n" ::"r"(sa), "l"(g));
}
DI void cp_commit() { asm volatile("cp.async.commit_group;\n"); }
template <int N> DI void cp_wait() { asm volatile("cp.async.wait_group %0;\n" ::"n"(N)); }

DI void ldm_x4(uint32_t& r0, uint32_t& r1, uint32_t& r2, uint32_t& r3, const void* s) {
    uint32_t sa = (uint32_t)__cvta_generic_to_shared(s);
    asm volatile("ldmatrix.sync.aligned.m8n8.x4.shared.b16 {%0,%1,%2,%3},[%4];"
                 : "=r"(r0), "=r"(r1), "=r"(r2), "=r"(r3) : "r"(sa));
}
DI void mma16816(float* c, const uint32_t* a, const uint32_t* b) {
    asm volatile(
        "mma.sync.aligned.m16n8k16.row.col.f32.bf16.bf16.f32 "
        "{%0,%1,%2,%3},{%4,%5,%6,%7},{%8,%9},{%0,%1,%2,%3};"
        : "+f"(c[0]), "+f"(c[1]), "+f"(c[2]), "+f"(c[3])
        : "r"(a[0]), "r"(a[1]), "r"(a[2]), "r"(a[3]), "r"(b[0]), "r"(b[1]));
}

DI float warp_max(float v) {
    for (int o = 16; o; o >>= 1) v = fmaxf(v, __shfl_xor_sync(0xffffffffu, v, o));
    return v;
}

// scale = max(amax/127, 1e-8), exact rn division to match jnp bin boundaries
DI float load_scale(const unsigned* slot) {
    float amax = __uint_as_float(*slot);
    return fmaxf(__fdiv_rn(amax, 127.0f), 1e-8f);
}

// ---------------- 0: reset amax accumulators ------------------------------
__global__ void k_reset() {
    if (threadIdx.x < 4) g_amax[threadIdx.x] = 0u;
}

// ---------------- 1: per-tensor absolute max -------------------------------
__global__ void k_amax(const float* __restrict__ p, long long n, unsigned* __restrict__ slot) {
    float m = 0.0f;
    long long i = ((long long)blockIdx.x * blockDim.x + threadIdx.x) * 4;
    long long stride = (long long)gridDim.x * blockDim.x * 4;
    for (; i < n; i += stride) {
        float4 v = *(const float4*)(p + i);
        m = fmaxf(m, fmaxf(fmaxf(fabsf(v.x), fabsf(v.y)), fmaxf(fabsf(v.z), fabsf(v.w))));
    }
    m = warp_max(m);
    if ((threadIdx.x & 31) == 0) atomicMax(slot, __float_as_uint(m));
}

// ---------------- 2: quantize to integer-valued bf16 ------------------------
__global__ void k_quant(const float* __restrict__ p, __nv_bfloat16* __restrict__ q,
                        long long n, const unsigned* __restrict__ slot) {
    float s = load_scale(slot);
    long long i = (long long)blockIdx.x * blockDim.x + threadIdx.x;
    long long stride = (long long)gridDim.x * blockDim.x;
    long long n4 = n >> 2;
    for (; i < n4; i += stride) {
        float4 v = *(const float4*)(p + i * 4);
        float k0 = fminf(fmaxf(rintf(__fdiv_rn(v.x, s)), -127.f), 127.f);
        float k1 = fminf(fmaxf(rintf(__fdiv_rn(v.y, s)), -127.f), 127.f);
        float k2 = fminf(fmaxf(rintf(__fdiv_rn(v.z, s)), -127.f), 127.f);
        float k3 = fminf(fmaxf(rintf(__fdiv_rn(v.w, s)), -127.f), 127.f);
        __nv_bfloat162 p0 = __halves2bfloat162(__float2bfloat16(k0), __float2bfloat16(k1));
        __nv_bfloat162 p1 = __halves2bfloat162(__float2bfloat16(k2), __float2bfloat16(k3));
        ((__nv_bfloat162*)q)[i * 2]     = p0;
        ((__nv_bfloat162*)q)[i * 2 + 1] = p1;
    }
}

// ---------------- 3: LoRA T = X @ A^T  (M x K @ K x 16), k-split partials ---
// grid (M/32, K/256), block 256
__global__ void k_tpart(const float* __restrict__ X, const float* __restrict__ A,
                        int K, float* __restrict__ part) {
    constexpr int KC = 256;
    __shared__ float xs[32 * KC];
    __shared__ float as[16 * (KC + 4)];
    int tid = threadIdx.x;
    int m0 = blockIdx.x * 32;
    int k0 = blockIdx.y * KC;

    for (int idx = tid; idx < 32 * KC / 4; idx += 256) {
        int row = idx / (KC / 4), c = idx % (KC / 4);
        *(float4*)(xs + row * KC + c * 4) =
            *(const float4*)(X + (size_t)(m0 + row) * K + k0 + c * 4);
    }
    for (int idx = tid; idx < 16 * KC / 4; idx += 256) {
        int row = idx / (KC / 4), c = idx % (KC / 4);
        *(float4*)(as + row * (KC + 4) + c * 4) =
            *(const float4*)(A + (size_t)row * K + k0 + c * 4);
    }
    __syncthreads();

    int kt = tid & 7, rg = (tid >> 3) & 3, mg = tid >> 5;
    float acc[4][4];
#pragma unroll
    for (int a = 0; a < 4; a++)
#pragma unroll
        for (int b = 0; b < 4; b++) acc[a][b] = 0.0f;

#pragma unroll
    for (int i = 0; i < 8; i++) {
        int kb = kt * 4 + i * 32;
        float4 xv[4], av[4];
#pragma unroll
        for (int mi = 0; mi < 4; mi++) xv[mi] = *(const float4*)(xs + (mg * 4 + mi) * KC + kb);
#pragma unroll
        for (int ri = 0; ri < 4; ri++) av[ri] = *(const float4*)(as + (rg * 4 + ri) * (KC + 4) + kb);
#pragma unroll
        for (int mi = 0; mi < 4; mi++)
#pragma unroll
            for (int ri = 0; ri < 4; ri++) {
                float s = acc[mi][ri];
                s = fmaf(xv[mi].x, av[ri].x, s);
                s = fmaf(xv[mi].y, av[ri].y, s);
                s = fmaf(xv[mi].z, av[ri].z, s);
                s = fmaf(xv[mi].w, av[ri].w, s);
                acc[mi][ri] = s;
            }
    }
    __syncthreads();
    float* red = xs;  // reuse: [8][32][16]
#pragma unroll
    for (int mi = 0; mi < 4; mi++)
#pragma unroll
        for (int ri = 0; ri < 4; ri++)
            red[kt * 512 + (mg * 4 + mi) * 16 + rg * 4 + ri] = acc[mi][ri];
    __syncthreads();
    for (int o = tid; o < 512; o += 256) {
        float s = 0.0f;
#pragma unroll
        for (int c = 0; c < 8; c++) s += red[c * 512 + o];
        part[(size_t)blockIdx.y * ((size_t)M * R) + (size_t)(m0 + (o >> 4)) * 16 + (o & 15)] = s;
    }
}

__global__ void k_tred(const float* __restrict__ part, float* __restrict__ t, int nchunks) {
    int i = blockIdx.x * blockDim.x + threadIdx.x;  // < M*R
    float s = 0.0f;
    for (int c = 0; c < nchunks; c++) s += part[(size_t)c * ((size_t)M * R) + i];
    t[i] = s;
}

// ---------------- 4: main GEMM with fused epilogue --------------------------
// C[m,n] = sA*sB * (Amat @ Bmat^T)[m,n] + bias[n] + 2 * dot16(T[m], L[n])
// optional exact-erf gelu + amax tracking.
// Amat: [M,K] bf16 rowmajor; Bmat: [N,K] bf16 rowmajor. Tiles 128x128x32, 256 thr.
DI uint32_t sw_off(int row, int kc) { return (uint32_t)((row * 4 + (kc ^ ((row >> 1) & 3))) << 4); }

DI void load_stage(const __nv_bfloat16* Ag, const __nv_bfloat16* Bg,
                   char* As, char* Bs, int m0, int n0, int K, int kt, int tid) {
    int kbase = kt * 32;
#pragma unroll
    for (int i = 0; i < 2; i++) {
        int id = tid + i * 256;
        int row = id >> 2, kc = id & 3;
        cp16(As + sw_off(row, kc), Ag + (size_t)(m0 + row) * K + kbase + kc * 8);
    }
#pragma unroll
    for (int i = 0; i < 2; i++) {
        int id = tid + i * 256;
        int row = id >> 2, kc = id & 3;
        cp16(Bs + sw_off(row, kc), Bg + (size_t)(n0 + row) * K + kbase + kc * 8);
    }
}

DI void compute_stage(const char* As, const char* Bs, float (&acc)[4][4][4],
                      int lane, int wm, int wn) {
#pragma unroll
    for (int ks = 0; ks < 2; ks++) {
        uint32_t a[4][4], b[4][2];
#pragma unroll
        for (int mf = 0; mf < 4; mf++) {
            int row = wm * 64 + mf * 16 + (lane & 15);
            int kc = ks * 2 + (lane >> 4);
            ldm_x4(a[mf][0], a[mf][1], a[mf][2], a[mf][3], As + sw_off(row, kc));
        }
#pragma unroll
        for (int bg = 0; bg < 2; bg++) {
            int row = wn * 32 + bg * 16 + (lane & 7) + ((lane >> 4) << 3);
            int kc = ks * 2 + ((lane >> 3) & 1);
            uint32_t r0, r1, r2, r3;
            ldm_x4(r0, r1, r2, r3, Bs + sw_off(row, kc));
            b[bg * 2][0] = r0; b[bg * 2][1] = r1;
            b[bg * 2 + 1][0] = r2; b[bg * 2 + 1][1] = r3;
        }
#pragma unroll
        for (int mf = 0; mf < 4; mf++)
#pragma unroll
            for (int nf = 0; nf < 4; nf++) mma16816(acc[mf][nf], a[mf], b[nf]);
    }
}

DI float dot16(const float* t, const float* l) {
    float4 t0 = ((const float4*)t)[0], t1 = ((const float4*)t)[1];
    float4 t2 = ((const float4*)t)[2], t3 = ((const float4*)t)[3];
    float4 l0 = ((const float4*)l)[0], l1 = ((const float4*)l)[1];
    float4 l2 = ((const float4*)l)[2], l3 = ((const float4*)l)[3];
    float s = t0.x * l0.x;
    s = fmaf(t0.y, l0.y, s); s = fmaf(t0.z, l0.z, s); s = fmaf(t0.w, l0.w, s);
    s = fmaf(t1.x, l1.x, s); s = fmaf(t1.y, l1.y, s); s = fmaf(t1.z, l1.z, s); s = fmaf(t1.w, l1.w, s);
    s = fmaf(t2.x, l2.x, s); s = fmaf(t2.y, l2.y, s); s = fmaf(t2.z, l2.z, s); s = fmaf(t2.w, l2.w, s);
    s = fmaf(t3.x, l3.x, s); s = fmaf(t3.y, l3.y, s); s = fmaf(t3.z, l3.z, s); s = fmaf(t3.w, l3.w, s);
    return s;
}

template <bool GELU>
__global__ __launch_bounds__(256) void k_gemm(
    const __nv_bfloat16* __restrict__ Ag, const __nv_bfloat16* __restrict__ Bg,
    const float* __restrict__ bias, const float* __restrict__ Tg,
    const float* __restrict__ Lg, const unsigned* __restrict__ sAp,
    const unsigned* __restrict__ sBp, float* __restrict__ C,
    unsigned* __restrict__ amax_out, int Mdim, int N, int K) {
    __shared__ __align__(16) char smem[32768];  // 2 stages x (A 8KB + B 8KB)
    int tid = threadIdx.x;
    int lane = tid & 31, wid = tid >> 5;
    int wm = wid >> 2, wn = wid & 3;  // warp grid 2(m) x 4(n), warp tile 64x32
    int m0 = blockIdx.y * 128, n0 = blockIdx.x * 128;

    float acc[4][4][4];
#pragma unroll
    for (int a = 0; a < 4; a++)
#pragma unroll
        for (int b = 0; b < 4; b++)
#pragma unroll
            for (int c = 0; c < 4; c++) acc[a][b][c] = 0.0f;

    char* As0 = smem;
    char* Bs0 = smem + 8192;
    char* As1 = smem + 16384;
    char* Bs1 = smem + 24576;

    int KT = K / 32;
    load_stage(Ag, Bg, As0, Bs0, m0, n0, K, 0, tid);
    cp_commit();
    for (int t = 0; t < KT; ++t) {
        if (t + 1 < KT) {
            char* As = ((t + 1) & 1) ? As1 : As0;
            char* Bs = ((t + 1) & 1) ? Bs1 : Bs0;
            load_stage(Ag, Bg, As, Bs, m0, n0, K, t + 1, tid);
        }
        cp_commit();
        cp_wait<1>();
        __syncthreads();
        {
            const char* As = (t & 1) ? As1 : As0;
            const char* Bs = (t & 1) ? Bs1 : Bs0;
            compute_stage(As, Bs, acc, lane, wm, wn);
        }
        __syncthreads();
    }

    // ---- epilogue ----
    float sAB = load_scale(sAp) * load_scale(sBp);

    float* Tt = (float*)smem;       // [128][16]
    float* Lt = Tt + 2048;          // [128][16]
    float* Bt = Lt + 2048;          // [128]
    for (int i = tid; i < 512; i += 256)
        ((float4*)Tt)[i] = *(const float4*)(Tg + (size_t)(m0 + (i >> 2)) * 16 + (i & 3) * 4);
    for (int i = tid; i < 512; i += 256)
        ((float4*)Lt)[i] = *(const float4*)(Lg + (size_t)(n0 + (i >> 2)) * 16 + (i & 3) * 4);
    for (int i = tid; i < 128; i += 256) Bt[i] = bias[n0 + i];
    __syncthreads();

    float amx = 0.0f;
#pragma unroll
    for (int mf = 0; mf < 4; mf++)
#pragma unroll
        for (int rh = 0; rh < 2; rh++) {
            int ml = wm * 64 + mf * 16 + (lane >> 2) + rh * 8;
            const float* tp = Tt + ml * 16;
            size_t grow = (size_t)(m0 + ml) * N + n0;
#pragma unroll
            for (int nf = 0; nf < 4; nf++) {
                int nl0 = wn * 32 + nf * 8 + (lane & 3) * 2;
                float v0 = sAB * acc[mf][nf][rh * 2 + 0] + Bt[nl0] + 2.0f * dot16(tp, Lt + nl0 * 16);
                float v1 = sAB * acc[mf][nf][rh * 2 + 1] + Bt[nl0 + 1] + 2.0f * dot16(tp, Lt + (nl0 + 1) * 16);
                if (GELU) {
                    v0 = 0.5f * v0 * (1.0f + erff(v0 * 0.70710678118654752f));
                    v1 = 0.5f * v1 * (1.0f + erff(v1 * 0.70710678118654752f));
                    amx = fmaxf(amx, fmaxf(fabsf(v0), fabsf(v1)));
                }
                *(float2*)(C + grow + nl0) = make_float2(v0, v1);
            }
        }
    if (GELU) {
        amx = warp_max(amx);
        if (lane == 0) atomicMax(amax_out, __float_as_uint(amx));
    }
}

// ---------------- launcher --------------------------------------------------
extern "C" void kernel_launch(void* const* d_in, const int* in_sizes, int n_in,
                              void* d_out, int out_size) {
    const float* x      = (const float*)d_in[0];
    const float* w_fc   = (const float*)d_in[1];
    const float* b_fc   = (const float*)d_in[2];
    const float* A_fc   = (const float*)d_in[3];
    const float* B_fc   = (const float*)d_in[4];
    const float* w_proj = (const float*)d_in[5];
    const float* b_proj = (const float*)d_in[6];
    const float* A_proj = (const float*)d_in[7];
    const float* B_proj = (const float*)d_in[8];
    float* out = (float*)d_out;

    void *pKx, *pKwfc, *pKwpr, *ph, *pKh, *pt1, *pt2, *ptp, *pam;
    cudaGetSymbolAddress(&pKx, g_Kx);
    cudaGetSymbolAddress(&pKwfc, g_Kwfc);
    cudaGetSymbolAddress(&pKwpr, g_Kwpr);
    cudaGetSymbolAddress(&ph, g_h);
    cudaGetSymbolAddress(&pKh, g_Kh);
    cudaGetSymbolAddress(&pt1, g_t1);
    cudaGetSymbolAddress(&pt2, g_t2);
    cudaGetSymbolAddress(&ptp, g_tpart);
    cudaGetSymbolAddress(&pam, g_amax);

    __nv_bfloat16* Kx   = (__nv_bfloat16*)pKx;
    __nv_bfloat16* Kwfc = (__nv_bfloat16*)pKwfc;
    __nv_bfloat16* Kwpr = (__nv_bfloat16*)pKwpr;
    float* hbuf = (float*)ph;
    __nv_bfloat16* Kh = (__nv_bfloat16*)pKh;
    float* t1 = (float*)pt1;
    float* t2 = (float*)pt2;
    float* tp = (float*)ptp;
    unsigned* am = (unsigned*)pam;

    const long long nXD = (long long)M * D;    // 16.7M
    const long long nWfc = (long long)Hh * D;  // 16.7M
    const long long nH = (long long)M * Hh;    // 67M

    k_reset<<<1, 32>>>();

    k_amax<<<2048, 256>>>(x, nXD, am + 0);
    k_amax<<<2048, 256>>>(w_fc, nWfc, am + 1);
    k_amax<<<2048, 256>>>(w_proj, nWfc, am + 2);

    k_quant<<<4096, 256>>>(x, Kx, nXD, am + 0);
    k_quant<<<4096, 256>>>(w_fc, Kwfc, nWfc, am + 1);
    k_quant<<<4096, 256>>>(w_proj, Kwpr, nWfc, am + 2);

    // LoRA t1 = x @ A_fc^T
    k_tpart<<<dim3(M / 32, D / 256), 256>>>(x, A_fc, D, tp);
    k_tred<<<(M * R) / 256, 256>>>(tp, t1, D / 256);

    // GEMM1: h = gelu(sx*sw*(Kx@Kwfc^T) + b_fc + 2*(t1@B_fc^T)); amax(h) fused
    k_gemm<true><<<dim3(Hh / 128, M / 128), 256>>>(
        Kx, Kwfc, b_fc, t1, B_fc, am + 0, am + 1, hbuf, am + 3, M, Hh, D);

    // quantize h
    k_quant<<<8192, 256>>>(hbuf, Kh, nH, am + 3);

    // LoRA t2 = h @ A_proj^T
    k_tpart<<<dim3(M / 32, Hh / 256), 256>>>(hbuf, A_proj, Hh, tp);
    k_tred<<<(M * R) / 256, 256>>>(tp, t2, Hh / 256);

    // GEMM2: out = sh*sw*(Kh@Kwpr^T) + b_proj + 2*(t2@B_proj^T)
    k_gemm<false><<<dim3(D / 128, M / 128), 256>>>(
        Kh, Kwpr, b_proj, t2, B_proj, am + 3, am + 2, out, nullptr, M, D, Hh);
}

// round 4
// speedup vs baseline: 2.8603x; 2.8603x over previous
#include <cuda_runtime.h>
#include <cuda_bf16.h>
#include <cstdint>

#define DI __device__ __forceinline__

// Arch-specific feature gate: tcgen05 only exists in the sm_103a/sm_100a pass.
#if defined(__CUDA_ARCH_FEAT_SM103_ALL) || defined(__CUDA_ARCH_FEAT_SM100_ALL)
#define HAS_TCGEN05 1
#else
#define HAS_TCGEN05 0
#endif

// Problem sizes (fixed by the dataset)
constexpr int D  = 2048;
constexpr int Hh = 8192;
constexpr int R  = 16;
constexpr int M  = 8192;

// GEMM tiling (tcgen05 path)
constexpr int TM = 256, TN = 256, KC = 64, NSTAGE = 3;
constexpr int STAGE_BYTES = (TM + TN) * 128;                    // 64 KB
constexpr int SMEM_GEMM   = NSTAGE * STAGE_BYTES + 1024;
constexpr uint32_t IDESC  = (1u << 4) | (1u << 7) | (1u << 10)  // F32, BF16, BF16
                          | ((TN / 8) << 17) | (8u << 24);      // N=256, M=128
constexpr uint64_t DESC_BASE_SW128 =
    (2ull << 61) | (1ull << 46) | (64ull << 32) | (1ull << 16);

// ---------------- scratch -----------------------------------------------
__device__ __nv_bfloat16 g_Kx[M * D];
__device__ __nv_bfloat16 g_Kwfc[Hh * D];
__device__ __nv_bfloat16 g_Kwpr[D * Hh];
__device__ float         g_h[(size_t)M * Hh];
__device__ __nv_bfloat16 g_Kh[(size_t)M * Hh];
__device__ float         g_t1[M * R];
__device__ float         g_t2[M * R];
__device__ float         g_tpart[32 * M * R];
__device__ unsigned      g_amax[4];

// ---------------- common helpers ----------------------------------------
DI uint32_t smaddr(const void* p) { return (uint32_t)__cvta_generic_to_shared(p); }
DI void cp16(void* s, const void* g) {
    asm volatile("cp.async.cg.shared.global [%0], [%1], 16;\n" ::"r"(smaddr(s)), "l"(g));
}
DI void cp_commit() { asm volatile("cp.async.commit_group;\n"); }
template <int N> DI void cp_wait() { asm volatile("cp.async.wait_group %0;\n" ::"n"(N)); }

DI float warp_max(float v) {
    for (int o = 16; o; o >>= 1) v = fmaxf(v, __shfl_xor_sync(0xffffffffu, v, o));
    return v;
}
DI float load_scale(const unsigned* slot) {
    return fmaxf(__fdiv_rn(__uint_as_float(*slot), 127.0f), 1e-8f);
}

// mma.sync fallback helpers
DI void ldm_x4(uint32_t& r0, uint32_t& r1, uint32_t& r2, uint32_t& r3, const void* s) {
    asm volatile("ldmatrix.sync.aligned.m8n8.x4.shared.b16 {%0,%1,%2,%3},[%4];"
                 : "=r"(r0), "=r"(r1), "=r"(r2), "=r"(r3) : "r"(smaddr(s)));
}
DI void mma16816(float* c, const uint32_t* a, const uint32_t* b) {
    asm volatile(
        "mma.sync.aligned.m16n8k16.row.col.f32.bf16.bf16.f32 "
        "{%0,%1,%2,%3},{%4,%5,%6,%7},{%8,%9},{%0,%1,%2,%3};"
        : "+f"(c[0]), "+f"(c[1]), "+f"(c[2]), "+f"(c[3])
        : "r"(a[0]), "r"(a[1]), "r"(a[2]), "r"(a[3]), "r"(b[0]), "r"(b[1]));
}
DI float dot16(const float* t, const float* l) {
    float s = 0.f;
#pragma unroll
    for (int k = 0; k < 16; k++) s = fmaf(t[k], l[k], s);
    return s;
}

#if HAS_TCGEN05
DI uint64_t mkdesc(uint32_t a) { return DESC_BASE_SW128 | (uint64_t)((a >> 4) & 0x3FFF); }
DI void tc_mma(uint32_t d, uint64_t ad, uint64_t bd, uint32_t idesc, uint32_t en) {
    asm volatile(
        "{\n\t.reg .pred p;\n\tsetp.ne.u32 p, %4, 0;\n\t"
        "tcgen05.mma.cta_group::1.kind::f16 [%0], %1, %2, %3, {%5,%5,%5,%5}, p;\n\t}"
        :: "r"(d), "l"(ad), "l"(bd), "r"(idesc), "r"(en), "r"(0u) : "memory");
}
DI void tc_commit(uint32_t mbar) {
    asm volatile(
        "tcgen05.commit.cta_group::1.mbarrier::arrive::one.shared::cluster.b64 [%0];"
        :: "r"(mbar) : "memory");
}
DI void mbar_init(uint32_t a, uint32_t cnt) {
    asm volatile("mbarrier.init.shared.b64 [%0], %1;" ::"r"(a), "r"(cnt) : "memory");
}
DI void mbar_wait(uint32_t a, uint32_t parity) {
    asm volatile(
        "{\n\t.reg .pred P1;\n\t"
        "WAIT_%=:\n\t"
        "mbarrier.try_wait.parity.acquire.cta.shared::cta.b64 P1, [%0], %1, 0x989680;\n\t"
        "@P1 bra.uni DONE_%=;\n\t"
        "bra.uni WAIT_%=;\n\t"
        "DONE_%=:\n\t}"
        :: "r"(a), "r"(parity) : "memory");
}
DI void fence_async() { asm volatile("fence.proxy.async.shared::cta;" ::: "memory"); }
DI void tmem_fence_after() { asm volatile("tcgen05.fence::after_thread_sync;" ::: "memory"); }
DI void tmem_fence_before() { asm volatile("tcgen05.fence::before_thread_sync;" ::: "memory"); }
DI void tmem_wait_ld() { asm volatile("tcgen05.wait::ld.sync.aligned;" ::: "memory"); }

// packed f32x2
DI unsigned long long pk2(float a, float b) {
    unsigned long long r; asm("mov.b64 %0, {%1,%2};" : "=l"(r) : "f"(a), "f"(b)); return r;
}
DI void upk2(float& a, float& b, unsigned long long v) {
    asm("mov.b64 {%0,%1}, %2;" : "=f"(a), "=f"(b) : "l"(v));
}
DI unsigned long long fma2(unsigned long long a, unsigned long long b, unsigned long long c) {
    unsigned long long d;
    asm("fma.rn.f32x2 %0, %1, %2, %3;" : "=l"(d) : "l"(a), "l"(b), "l"(c));
    return d;
}

#define LDTM32(r, addr)                                                          \
    asm volatile(                                                                \
        "tcgen05.ld.sync.aligned.32x32b.x32.b32 "                                \
        "{%0,%1,%2,%3,%4,%5,%6,%7,%8,%9,%10,%11,%12,%13,%14,%15,"               \
        "%16,%17,%18,%19,%20,%21,%22,%23,%24,%25,%26,%27,%28,%29,%30,%31},[%32];"\
        : "=r"((r)[0]), "=r"((r)[1]), "=r"((r)[2]), "=r"((r)[3]),                \
          "=r"((r)[4]), "=r"((r)[5]), "=r"((r)[6]), "=r"((r)[7]),                \
          "=r"((r)[8]), "=r"((r)[9]), "=r"((r)[10]), "=r"((r)[11]),              \
          "=r"((r)[12]), "=r"((r)[13]), "=r"((r)[14]), "=r"((r)[15]),            \
          "=r"((r)[16]), "=r"((r)[17]), "=r"((r)[18]), "=r"((r)[19]),            \
          "=r"((r)[20]), "=r"((r)[21]), "=r"((r)[22]), "=r"((r)[23]),            \
          "=r"((r)[24]), "=r"((r)[25]), "=r"((r)[26]), "=r"((r)[27]),            \
          "=r"((r)[28]), "=r"((r)[29]), "=r"((r)[30]), "=r"((r)[31])             \
        : "r"(addr))
#endif  // HAS_TCGEN05

// ---------------- 0: reset ----------------------------------------------
__global__ void k_reset() { if (threadIdx.x < 4) g_amax[threadIdx.x] = 0u; }

// ---------------- 1: per-tensor abs max ----------------------------------
__global__ void k_amax(const float* __restrict__ p, long long n, unsigned* __restrict__ slot) {
    float m = 0.0f;
    long long i = ((long long)blockIdx.x * blockDim.x + threadIdx.x) * 4;
    long long stride = (long long)gridDim.x * blockDim.x * 4;
    for (; i < n; i += stride) {
        float4 v = *(const float4*)(p + i);
        m = fmaxf(m, fmaxf(fmaxf(fabsf(v.x), fabsf(v.y)), fmaxf(fabsf(v.z), fabsf(v.w))));
    }
    m = warp_max(m);
    if ((threadIdx.x & 31) == 0) atomicMax(slot, __float_as_uint(m));
}

// ---------------- 2: quantize (weights) ----------------------------------
__global__ void k_quant(const float* __restrict__ p, __nv_bfloat16* __restrict__ q,
                        long long n, const unsigned* __restrict__ slot) {
    float s = load_scale(slot);
    long long i = (long long)blockIdx.x * blockDim.x + threadIdx.x;
    long long stride = (long long)gridDim.x * blockDim.x;
    long long n4 = n >> 2;
    for (; i < n4; i += stride) {
        float4 v = *(const float4*)(p + i * 4);
        float k0 = fminf(fmaxf(rintf(__fdiv_rn(v.x, s)), -127.f), 127.f);
        float k1 = fminf(fmaxf(rintf(__fdiv_rn(v.y, s)), -127.f), 127.f);
        float k2 = fminf(fmaxf(rintf(__fdiv_rn(v.z, s)), -127.f), 127.f);
        float k3 = fminf(fmaxf(rintf(__fdiv_rn(v.w, s)), -127.f), 127.f);
        ((__nv_bfloat162*)q)[i * 2]     = __halves2bfloat162(__float2bfloat16(k0), __float2bfloat16(k1));
        ((__nv_bfloat162*)q)[i * 2 + 1] = __halves2bfloat162(__float2bfloat16(k2), __float2bfloat16(k3));
    }
}

// ---------------- 3: LoRA partials + fused quantization -------------------
__global__ void k_tpart_q(const float* __restrict__ X, const float* __restrict__ A,
                          int K, float* __restrict__ part,
                          __nv_bfloat16* __restrict__ q, const unsigned* __restrict__ slot) {
    constexpr int KC2 = 256;
    __shared__ float xs[32 * KC2];
    __shared__ float as[16 * (KC2 + 4)];
    float s = load_scale(slot);
    int tid = threadIdx.x;
    int m0 = blockIdx.x * 32;
    int k0 = blockIdx.y * KC2;

    for (int idx = tid; idx < 32 * KC2 / 4; idx += 256) {
        int row = idx / (KC2 / 4), c = idx % (KC2 / 4);
        size_t gidx = (size_t)(m0 + row) * K + k0 + c * 4;
        float4 v = *(const float4*)(X + gidx);
        *(float4*)(xs + row * KC2 + c * 4) = v;
        float q0 = fminf(fmaxf(rintf(__fdiv_rn(v.x, s)), -127.f), 127.f);
        float q1 = fminf(fmaxf(rintf(__fdiv_rn(v.y, s)), -127.f), 127.f);
        float q2 = fminf(fmaxf(rintf(__fdiv_rn(v.z, s)), -127.f), 127.f);
        float q3 = fminf(fmaxf(rintf(__fdiv_rn(v.w, s)), -127.f), 127.f);
        ((__nv_bfloat162*)q)[gidx / 2]     = __halves2bfloat162(__float2bfloat16(q0), __float2bfloat16(q1));
        ((__nv_bfloat162*)q)[gidx / 2 + 1] = __halves2bfloat162(__float2bfloat16(q2), __float2bfloat16(q3));
    }
    for (int idx = tid; idx < 16 * KC2 / 4; idx += 256) {
        int row = idx / (KC2 / 4), c = idx % (KC2 / 4);
        *(float4*)(as + row * (KC2 + 4) + c * 4) =
            *(const float4*)(A + (size_t)row * K + k0 + c * 4);
    }
    __syncthreads();

    int kt = tid & 7, rg = (tid >> 3) & 3, mg = tid >> 5;
    float acc[4][4];
#pragma unroll
    for (int a = 0; a < 4; a++)
#pragma unroll
        for (int b = 0; b < 4; b++) acc[a][b] = 0.0f;
#pragma unroll
    for (int i = 0; i < 8; i++) {
        int kb = kt * 4 + i * 32;
        float4 xv[4], av[4];
#pragma unroll
        for (int mi = 0; mi < 4; mi++) xv[mi] = *(const float4*)(xs + (mg * 4 + mi) * KC2 + kb);
#pragma unroll
        for (int ri = 0; ri < 4; ri++) av[ri] = *(const float4*)(as + (rg * 4 + ri) * (KC2 + 4) + kb);
#pragma unroll
        for (int mi = 0; mi < 4; mi++)
#pragma unroll
            for (int ri = 0; ri < 4; ri++) {
                float v = acc[mi][ri];
                v = fmaf(xv[mi].x, av[ri].x, v); v = fmaf(xv[mi].y, av[ri].y, v);
                v = fmaf(xv[mi].z, av[ri].z, v); v = fmaf(xv[mi].w, av[ri].w, v);
                acc[mi][ri] = v;
            }
    }
    __syncthreads();
    float* red = xs;
#pragma unroll
    for (int mi = 0; mi < 4; mi++)
#pragma unroll
        for (int ri = 0; ri < 4; ri++)
            red[kt * 512 + (mg * 4 + mi) * 16 + rg * 4 + ri] = acc[mi][ri];
    __syncthreads();
    for (int o = tid; o < 512; o += 256) {
        float v = 0.0f;
#pragma unroll
        for (int c = 0; c < 8; c++) v += red[c * 512 + o];
        part[(size_t)blockIdx.y * ((size_t)M * R) + (size_t)(m0 + (o >> 4)) * 16 + (o & 15)] = v;
    }
}

__global__ void k_tred(const float* __restrict__ part, float* __restrict__ t, int nchunks) {
    int i = blockIdx.x * blockDim.x + threadIdx.x;
    float s = 0.0f;
    for (int c = 0; c < nchunks; c++) s += part[(size_t)c * ((size_t)M * R) + i];
    t[i] = s;
}

// ---- fallback mma.sync building blocks (used only in non-'a' pass) -------
DI uint32_t sw_off_f(int row, int kc) { return (uint32_t)((row * 4 + (kc ^ ((row >> 1) & 3))) << 4); }

DI void load_stage_f(const __nv_bfloat16* Ag, const __nv_bfloat16* Bg,
                     char* As, char* Bs, int m0, int n0, int K, int kt, int tid) {
    int kbase = kt * 32;
#pragma unroll
    for (int i = 0; i < 2; i++) {
        int id = tid + i * 256;
        int row = id >> 2, kc = id & 3;
        cp16(As + sw_off_f(row, kc), Ag + (size_t)(m0 + row) * K + kbase + kc * 8);
    }
#pragma unroll
    for (int i = 0; i < 2; i++) {
        int id = tid + i * 256;
        int row = id >> 2, kc = id & 3;
        cp16(Bs + sw_off_f(row, kc), Bg + (size_t)(n0 + row) * K + kbase + kc * 8);
    }
}

DI void compute_stage_f(const char* As, const char* Bs, float (&acc)[4][4][4],
                        int lane, int wm, int wn) {
#pragma unroll
    for (int ks = 0; ks < 2; ks++) {
        uint32_t a[4][4], b[4][2];
#pragma unroll
        for (int mf = 0; mf < 4; mf++) {
            int row = wm * 64 + mf * 16 + (lane & 15);
            int kc = ks * 2 + (lane >> 4);
            ldm_x4(a[mf][0], a[mf][1], a[mf][2], a[mf][3], As + sw_off_f(row, kc));
        }
#pragma unroll
        for (int bg = 0; bg < 2; bg++) {
            int row = wn * 32 + bg * 16 + (lane & 7) + ((lane >> 4) << 3);
            int kc = ks * 2 + ((lane >> 3) & 1);
            uint32_t r0, r1, r2, r3;
            ldm_x4(r0, r1, r2, r3, Bs + sw_off_f(row, kc));
            b[bg * 2][0] = r0; b[bg * 2][1] = r1;
            b[bg * 2 + 1][0] = r2; b[bg * 2 + 1][1] = r3;
        }
#pragma unroll
        for (int mf = 0; mf < 4; mf++)
#pragma unroll
            for (int nf = 0; nf < 4; nf++) mma16816(acc[mf][nf], a[mf], b[nf]);
    }
}

// ---------------- 4: main GEMM (dual-path) --------------------------------
// C[m,n] = sA*sB*(A@B^T) + bias[n] + 2*dot16(T[m],L[n]) (+ gelu + amax)
template <bool GELU>
__global__ __launch_bounds__(256) void k_gemm_tc(
    const __nv_bfloat16* __restrict__ Ag, const __nv_bfloat16* __restrict__ Bg,
    const float* __restrict__ bias, const float* __restrict__ Tg,
    const float* __restrict__ Lg, const unsigned* __restrict__ sAp,
    const unsigned* __restrict__ sBp, float* __restrict__ C,
    unsigned* __restrict__ amax_out, int N, int K) {
    extern __shared__ char ds_raw[];
    int tid = threadIdx.x;
    int lane = tid & 31, wid = tid >> 5;
    int m0 = blockIdx.y * TM, n0 = blockIdx.x * TN;

#if HAS_TCGEN05
    __shared__ __align__(8) unsigned long long s_mbar[NSTAGE];
    __shared__ uint32_t s_tmem;

    uint32_t dsu_raw = smaddr(ds_raw);
    uint32_t dsb = (dsu_raw + 1023u) & ~1023u;
    char* ds = ds_raw + (dsb - dsu_raw);

    if (tid == 0)
        for (int s = 0; s < NSTAGE; s++) mbar_init(smaddr(&s_mbar[s]), 1);
    if (wid == 0) {
        asm volatile("tcgen05.alloc.cta_group::1.sync.aligned.shared::cta.b32 [%0], %1;"
                     ::"r"(smaddr(&s_tmem)), "r"(512u) : "memory");
        asm volatile("tcgen05.relinquish_alloc_permit.cta_group::1.sync.aligned;");
    }
    __syncthreads();
    uint32_t tb = s_tmem;

    const int NCk = K / KC;
    int ph[NSTAGE] = {0, 0, 0};

    auto load_tile = [&](char* stage, int kbase) {
#pragma unroll
        for (int i = 0; i < 8; i++) {
            int id = tid + (i << 8);
            int r = id >> 3, c = id & 7;
            cp16(stage + r * 128 + (((c ^ (r & 7)) << 4)),
                 Ag + (size_t)(m0 + r) * K + kbase + (c << 3));
        }
#pragma unroll
        for (int i = 0; i < 8; i++) {
            int id = tid + (i << 8);
            int r = id >> 3, c = id & 7;
            cp16(stage + TM * 128 + r * 128 + ((c ^ (r & 7)) << 4),
                 Bg + (size_t)(n0 + r) * K + kbase + (c << 3));
        }
        cp_commit();
    };

    load_tile(ds, 0);
    load_tile(ds + STAGE_BYTES, KC);

    for (int c = 0; c < NCk; c++) {
        int s = c % NSTAGE;
        if (c + 2 < NCk) cp_wait<1>(); else cp_wait<0>();
        __syncthreads();
        if (tid == 0) {
            fence_async();
            uint64_t ad = mkdesc(dsb + s * STAGE_BYTES);
            uint64_t bd = mkdesc(dsb + s * STAGE_BYTES + TM * 128);
#pragma unroll
            for (int ks = 0; ks < KC / 16; ks++) {
                uint32_t en = (c > 0 || ks > 0) ? 1u : 0u;
                tc_mma(tb,       ad + ks * 2,        bd + ks * 2, IDESC, en);
                tc_mma(tb + 256, ad + ks * 2 + 1024, bd + ks * 2, IDESC, en);
            }
            tc_commit(smaddr(&s_mbar[s]));
        }
        if (c + 2 < NCk) {
            int s2 = (c + 2) % NSTAGE;
            if (c >= 1) { mbar_wait(smaddr(&s_mbar[s2]), ph[s2]); ph[s2] ^= 1; }
            load_tile(ds + s2 * STAGE_BYTES, (c + 2) * KC);
        }
    }
    { int sf = (NCk - 1) % NSTAGE; mbar_wait(smaddr(&s_mbar[sf]), ph[sf]); }
    tmem_fence_after();
    __syncthreads();

    // ---- epilogue ----
    float sAB = load_scale(sAp) * load_scale(sBp);
    float* Ls  = (float*)ds;            // interleaved L pairs, 16KB
    float* Bs  = (float*)(ds + 16384);  // [TN] bias
    float* Stg = (float*)(ds + 17408);  // 8 warps x 32x36 floats

    for (int i = tid; i < TN * R; i += 256) {
        int n = i >> 4, k = i & 15;
        Ls[((n >> 1) << 5) + (k << 1) + (n & 1)] = Lg[(size_t)(n0 + n) * R + k];
    }
    Bs[tid] = bias[n0 + tid];
    __syncthreads();

    int blk = wid >> 2;
    int rowbase = blk * 128 + (wid & 3) * 32;
    int row_local = rowbase + lane;

    unsigned long long Tp[16];
    {
        const float* tg = Tg + (size_t)(m0 + row_local) * R;
#pragma unroll
        for (int k = 0; k < 16; k++) { float tv = 2.0f * tg[k]; Tp[k] = pk2(tv, tv); }
    }
    unsigned long long s2pk = pk2(sAB, sAB);
    float amx = 0.0f;
    float* stg = Stg + wid * (32 * 36);
    size_t crowbase = (size_t)(m0 + rowbase) * N + n0;

    for (int cb = 0; cb < TN; cb += 32) {
        uint32_t d[32];
        LDTM32(d, tb + blk * 256 + cb);
        tmem_wait_ld();
        float vout[32];
#pragma unroll
        for (int j = 0; j < 16; j++) {
            int n2 = cb + 2 * j;
            const unsigned long long* lp = (const unsigned long long*)(Ls + ((n2 >> 1) << 5));
            unsigned long long acc = pk2(Bs[n2], Bs[n2 + 1]);
#pragma unroll
            for (int k = 0; k < 16; k++) acc = fma2(Tp[k], lp[k], acc);
            unsigned long long d2 = pk2(__uint_as_float(d[2 * j]), __uint_as_float(d[2 * j + 1]));
            unsigned long long v2 = fma2(s2pk, d2, acc);
            float v0, v1; upk2(v0, v1, v2);
            if (GELU) {
                v0 = 0.5f * v0 * (1.0f + erff(v0 * 0.70710678118654752f));
                v1 = 0.5f * v1 * (1.0f + erff(v1 * 0.70710678118654752f));
                amx = fmaxf(amx, fmaxf(fabsf(v0), fabsf(v1)));
            }
            vout[2 * j] = v0; vout[2 * j + 1] = v1;
        }
#pragma unroll
        for (int q = 0; q < 8; q++) *(float4*)(stg + lane * 36 + q * 4) = *(float4*)(vout + q * 4);
        __syncwarp();
#pragma unroll
        for (int rr = 0; rr < 8; rr++) {
            int r = rr * 4 + (lane >> 3);
            float4 v = *(const float4*)(stg + r * 36 + (lane & 7) * 4);
            *(float4*)(C + crowbase + (size_t)r * N + cb + (lane & 7) * 4) = v;
        }
        __syncwarp();
    }
    if (GELU) {
        amx = warp_max(amx);
        if (lane == 0) atomicMax(amax_out, __float_as_uint(amx));
    }
    tmem_fence_before();
    __syncthreads();
    if (wid == 0)
        asm volatile("tcgen05.dealloc.cta_group::1.sync.aligned.b32 %0, %1;"
                     ::"r"(tb), "r"(512u));

#else  // ---------------- fallback: mma.sync, 4 quadrants ----------------
    char* ds = ds_raw;
    char* As0 = ds;
    char* Bs0 = ds + 8192;
    char* As1 = ds + 16384;
    char* Bs1 = ds + 24576;
    int wm = wid >> 2, wn = wid & 3;
    float sAB = load_scale(sAp) * load_scale(sBp);
    float amx_all = 0.0f;

    for (int quad = 0; quad < 4; quad++) {
        int m0q = m0 + (quad >> 1) * 128;
        int n0q = n0 + (quad & 1) * 128;
        __syncthreads();

        float acc[4][4][4];
#pragma unroll
        for (int a = 0; a < 4; a++)
#pragma unroll
            for (int b = 0; b < 4; b++)
#pragma unroll
                for (int c = 0; c < 4; c++) acc[a][b][c] = 0.0f;

        int KT = K / 32;
        load_stage_f(Ag, Bg, As0, Bs0, m0q, n0q, K, 0, tid);
        cp_commit();
        for (int t = 0; t < KT; ++t) {
            if (t + 1 < KT) {
                char* As = ((t + 1) & 1) ? As1 : As0;
                char* Bs = ((t + 1) & 1) ? Bs1 : Bs0;
                load_stage_f(Ag, Bg, As, Bs, m0q, n0q, K, t + 1, tid);
            }
            cp_commit();
            cp_wait<1>();
            __syncthreads();
            {
                const char* As = (t & 1) ? As1 : As0;
                const char* Bs = (t & 1) ? Bs1 : Bs0;
                compute_stage_f(As, Bs, acc, lane, wm, wn);
            }
            __syncthreads();
        }

        float* Tt = (float*)ds;
        float* Lt = Tt + 2048;
        float* Bt = Lt + 2048;
        for (int i = tid; i < 512; i += 256)
            ((float4*)Tt)[i] = *(const float4*)(Tg + (size_t)(m0q + (i >> 2)) * 16 + (i & 3) * 4);
        for (int i = tid; i < 512; i += 256)
            ((float4*)Lt)[i] = *(const float4*)(Lg + (size_t)(n0q + (i >> 2)) * 16 + (i & 3) * 4);
        for (int i = tid; i < 128; i += 256) Bt[i] = bias[n0q + i];
        __syncthreads();

#pragma unroll
        for (int mf = 0; mf < 4; mf++)
#pragma unroll
            for (int rh = 0; rh < 2; rh++) {
                int ml = wm * 64 + mf * 16 + (lane >> 2) + rh * 8;
                const float* tp = Tt + ml * 16;
                size_t grow = (size_t)(m0q + ml) * N + n0q;
#pragma unroll
                for (int nf = 0; nf < 4; nf++) {
                    int nl0 = wn * 32 + nf * 8 + (lane & 3) * 2;
                    float v0 = sAB * acc[mf][nf][rh * 2 + 0] + Bt[nl0] + 2.0f * dot16(tp, Lt + nl0 * 16);
                    float v1 = sAB * acc[mf][nf][rh * 2 + 1] + Bt[nl0 + 1] + 2.0f * dot16(tp, Lt + (nl0 + 1) * 16);
                    if (GELU) {
                        v0 = 0.5f * v0 * (1.0f + erff(v0 * 0.70710678118654752f));
                        v1 = 0.5f * v1 * (1.0f + erff(v1 * 0.70710678118654752f));
                        amx_all = fmaxf(amx_all, fmaxf(fabsf(v0), fabsf(v1)));
                    }
                    *(float2*)(C + grow + nl0) = make_float2(v0, v1);
                }
            }
    }
    if (GELU) {
        amx_all = warp_max(amx_all);
        if (lane == 0) atomicMax(amax_out, __float_as_uint(amx_all));
    }
#endif
}

// ---------------- launcher ----------------------------------------------
extern "C" void kernel_launch(void* const* d_in, const int* in_sizes, int n_in,
                              void* d_out, int out_size) {
    const float* x      = (const float*)d_in[0];
    const float* w_fc   = (const float*)d_in[1];
    const float* b_fc   = (const float*)d_in[2];
    const float* A_fc   = (const float*)d_in[3];
    const float* B_fc   = (const float*)d_in[4];
    const float* w_proj = (const float*)d_in[5];
    const float* b_proj = (const float*)d_in[6];
    const float* A_proj = (const float*)d_in[7];
    const float* B_proj = (const float*)d_in[8];
    float* out = (float*)d_out;

    void *pKx, *pKwfc, *pKwpr, *ph, *pKh, *pt1, *pt2, *ptp, *pam;
    cudaGetSymbolAddress(&pKx, g_Kx);
    cudaGetSymbolAddress(&pKwfc, g_Kwfc);
    cudaGetSymbolAddress(&pKwpr, g_Kwpr);
    cudaGetSymbolAddress(&ph, g_h);
    cudaGetSymbolAddress(&pKh, g_Kh);
    cudaGetSymbolAddress(&pt1, g_t1);
    cudaGetSymbolAddress(&pt2, g_t2);
    cudaGetSymbolAddress(&ptp, g_tpart);
    cudaGetSymbolAddress(&pam, g_amax);

    __nv_bfloat16* Kx   = (__nv_bfloat16*)pKx;
    __nv_bfloat16* Kwfc = (__nv_bfloat16*)pKwfc;
    __nv_bfloat16* Kwpr = (__nv_bfloat16*)pKwpr;
    float* hbuf = (float*)ph;
    __nv_bfloat16* Kh = (__nv_bfloat16*)pKh;
    float* t1 = (float*)pt1;
    float* t2 = (float*)pt2;
    float* tp = (float*)ptp;
    unsigned* am = (unsigned*)pam;

    cudaFuncSetAttribute(k_gemm_tc<true>,  cudaFuncAttributeMaxDynamicSharedMemorySize, SMEM_GEMM);
    cudaFuncSetAttribute(k_gemm_tc<false>, cudaFuncAttributeMaxDynamicSharedMemorySize, SMEM_GEMM);

    const long long nXD  = (long long)M * D;
    const long long nWfc = (long long)Hh * D;

    k_reset<<<1, 32>>>();

    k_amax<<<2048, 256>>>(x, nXD, am + 0);
    k_amax<<<2048, 256>>>(w_fc, nWfc, am + 1);
    k_amax<<<2048, 256>>>(w_proj, nWfc, am + 2);

    k_quant<<<4096, 256>>>(w_fc, Kwfc, nWfc, am + 1);
    k_quant<<<4096, 256>>>(w_proj, Kwpr, nWfc, am + 2);

    // LoRA t1 = x @ A_fc^T, fused quantize x -> Kx
    k_tpart_q<<<dim3(M / 32, D / 256), 256>>>(x, A_fc, D, tp, Kx, am + 0);
    k_tred<<<(M * R) / 256, 256>>>(tp, t1, D / 256);

    // GEMM1: h = gelu(sx*sw*(Kx@Kwfc^T) + b_fc + 2*(t1@B_fc^T)), amax(h) fused
    k_gemm_tc<true><<<dim3(Hh / TN, M / TM), 256, SMEM_GEMM>>>(
        Kx, Kwfc, b_fc, t1, B_fc, am + 0, am + 1, hbuf, am + 3, Hh, D);

    // LoRA t2 = h @ A_proj^T, fused quantize h -> Kh
    k_tpart_q<<<dim3(M / 32, Hh / 256), 256>>>(hbuf, A_proj, Hh, tp, Kh, am + 3);
    k_tred<<<(M * R) / 256, 256>>>(tp, t2, Hh / 256);

    // GEMM2
    k_gemm_tc<false><<<dim3(D / TN, M / TM), 256, SMEM_GEMM>>>(
        Kh, Kwpr, b_proj, t2, B_proj, am + 3, am + 2, out, nullptr, D, Hh);
}